// round 1
// baseline (speedup 1.0000x reference)
#include <cuda_runtime.h>
#include <cuda_bf16.h>
#include <math.h>

// GRNNTransformGated: 13-level binary-tree GRNN.
// B=64, LVLS=13, F=7, H=64. SIZES[j] = 64<<j, OFFS[j] = 64*((1<<j)-1).
//
// Level j (j = 12..0):
//   u   = relu(c @ W_u^T + b_u)                        (n,64)
//   j==12: up = u
//   hhu = [up[0::2], up[1::2], u]                      (n,192)
//   r   = sigmoid(hhu @ W_r^T + b_r)                   (n,192)
//   h_H = relu((r*hhu) @ W_h^T + b_h)                  (n,64)
//   z   = [h_H, hhu] @ W_z^T + b_z                     (n,256)
//   g   = softmax(z.reshape(n,4,64), axis=1)
//   up  = g0*h_H + g1*h_L + g2*h_R + g3*u              (n,64)

#define NTHR 256
#define SB 260   // Bs row stride (floats), padded vs 256 for bank spread

// Scratch ping-pong buffers (device globals: allocation-free).
__device__ float g_upA[262144 * 64];   // 67 MB
__device__ float g_upB[131072 * 64];   // 33.5 MB

// ---------------- top level (j=12): up = relu(c @ W_u^T + b_u) ----------------
__global__ void grnn_top_kernel(const float* __restrict__ contents,
                                const float* __restrict__ W_u,
                                const float* __restrict__ b_u,
                                float* __restrict__ up, int n) {
    int idx = blockIdx.x * blockDim.x + threadIdx.x;
    if (idx >= n * 64) return;
    int i = idx >> 6, h = idx & 63;
    const float* c = contents + (size_t)i * 7;
    const float* w = W_u + h * 7;
    float acc = b_u[h];
#pragma unroll
    for (int f = 0; f < 7; f++) acc = fmaf(__ldg(c + f), __ldg(w + f), acc);
    up[idx] = fmaxf(acc, 0.f);
}

// ---------------- fused level kernel: 64 rows per block ----------------
__global__ __launch_bounds__(NTHR) void grnn_level_kernel(
    const float* __restrict__ contents,  // n x 7 (already offset to this level)
    const float* __restrict__ up_prev,   // 2n x 64
    float* __restrict__ up_out,          // n x 64
    const float* __restrict__ W_u, const float* __restrict__ b_u,
    const float* __restrict__ W_r, const float* __restrict__ b_r,
    const float* __restrict__ W_h, const float* __restrict__ b_h,
    const float* __restrict__ W_z, const float* __restrict__ b_z)
{
    extern __shared__ float sm[];
    float* hhu = sm;                     // 64*192 = 12288
    float* rx  = hhu + 64 * 192;         // 64*192 = 12288
    float* hH  = rx  + 64 * 192;         // 64*64  = 4096
    float* Bs  = hH  + 64 * 64;          // 16*SB  = 4160
    float* cs  = Bs  + 16 * SB;          // 64*8   = 512
    float* wu  = cs  + 64 * 8;           // 64*8   = 512
    float* bus = wu  + 64 * 8;           // 64

    const int t  = threadIdx.x;
    const int tx = t & 15, ty = t >> 4;
    const int r0 = blockIdx.x * 64;

    // ---- phase 0: build hhu = [h_L | h_R | u] ----
    for (int idx = t; idx < 64 * 7; idx += NTHR) {
        int i = idx / 7, f = idx % 7;
        cs[i * 8 + f] = contents[(size_t)(r0 + i) * 7 + f];
        wu[i * 8 + f] = W_u[idx];
    }
    if (t < 64) bus[t] = b_u[t];
    for (int idx = t; idx < 64 * 128; idx += NTHR) {
        int i = idx >> 7, c = idx & 127;
        hhu[i * 192 + c] = up_prev[((size_t)2 * (r0 + i) + (c >> 6)) * 64 + (c & 63)];
    }
    __syncthreads();
#pragma unroll
    for (int p = 0; p < 16; p++) {
        int idx = t + p * NTHR;
        int i = idx >> 6, h = idx & 63;
        float acc = bus[h];
#pragma unroll
        for (int f = 0; f < 7; f++) acc = fmaf(cs[i * 8 + f], wu[h * 8 + f], acc);
        hhu[i * 192 + 128 + h] = fmaxf(acc, 0.f);
    }
    __syncthreads();

    // ---- phase 1: rx = sigmoid(hhu @ W_r^T + b_r) * hhu   (O=192, K=192) ----
    {
        float acc[4][12];
#pragma unroll
        for (int j = 0; j < 4; j++)
#pragma unroll
            for (int m = 0; m < 12; m++) acc[j][m] = 0.f;

        for (int kc = 0; kc < 12; kc++) {
            __syncthreads();
#pragma unroll
            for (int p = 0; p < 3; p++) {
                int o = p * 64 + (t >> 2);
                int kq = (t & 3) * 4;
                float4 v = *reinterpret_cast<const float4*>(&W_r[o * 192 + kc * 16 + kq]);
                Bs[(kq + 0) * SB + o] = v.x;
                Bs[(kq + 1) * SB + o] = v.y;
                Bs[(kq + 2) * SB + o] = v.z;
                Bs[(kq + 3) * SB + o] = v.w;
            }
            __syncthreads();
#pragma unroll
            for (int k = 0; k < 16; k++) {
                float a[4], b[12];
#pragma unroll
                for (int j = 0; j < 4; j++) a[j] = hhu[(ty * 4 + j) * 192 + kc * 16 + k];
#pragma unroll
                for (int m = 0; m < 12; m++) b[m] = Bs[k * SB + tx * 12 + m];
#pragma unroll
                for (int j = 0; j < 4; j++)
#pragma unroll
                    for (int m = 0; m < 12; m++) acc[j][m] = fmaf(a[j], b[m], acc[j][m]);
            }
        }
        __syncthreads();
#pragma unroll
        for (int j = 0; j < 4; j++)
#pragma unroll
            for (int m = 0; m < 12; m++) {
                int i = ty * 4 + j, o = tx * 12 + m;
                float rv = 1.f / (1.f + __expf(-(acc[j][m] + __ldg(b_r + o))));
                rx[i * 192 + o] = rv * hhu[i * 192 + o];
            }
    }
    __syncthreads();

    // ---- phase 2: h_H = relu(rx @ W_h^T + b_h)   (O=64, K=192) ----
    {
        float acc[4][4];
#pragma unroll
        for (int j = 0; j < 4; j++)
#pragma unroll
            for (int m = 0; m < 4; m++) acc[j][m] = 0.f;

        for (int kc = 0; kc < 12; kc++) {
            __syncthreads();
            {
                int o = t >> 2;
                int kq = (t & 3) * 4;
                float4 v = *reinterpret_cast<const float4*>(&W_h[o * 192 + kc * 16 + kq]);
                Bs[(kq + 0) * SB + o] = v.x;
                Bs[(kq + 1) * SB + o] = v.y;
                Bs[(kq + 2) * SB + o] = v.z;
                Bs[(kq + 3) * SB + o] = v.w;
            }
            __syncthreads();
#pragma unroll
            for (int k = 0; k < 16; k++) {
                float a[4], b[4];
#pragma unroll
                for (int j = 0; j < 4; j++) a[j] = rx[(ty * 4 + j) * 192 + kc * 16 + k];
#pragma unroll
                for (int m = 0; m < 4; m++) b[m] = Bs[k * SB + tx * 4 + m];
#pragma unroll
                for (int j = 0; j < 4; j++)
#pragma unroll
                    for (int m = 0; m < 4; m++) acc[j][m] = fmaf(a[j], b[m], acc[j][m]);
            }
        }
        __syncthreads();
#pragma unroll
        for (int j = 0; j < 4; j++)
#pragma unroll
            for (int m = 0; m < 4; m++) {
                int i = ty * 4 + j, o = tx * 4 + m;
                hH[i * 64 + o] = fmaxf(acc[j][m] + __ldg(b_h + o), 0.f);
            }
    }
    __syncthreads();

    // ---- phase 3: z = [h_H | hhu] @ W_z^T + b_z; softmax over 4 groups; combine ----
    {
        float acc[4][16];
#pragma unroll
        for (int j = 0; j < 4; j++)
#pragma unroll
            for (int m = 0; m < 16; m++) acc[j][m] = 0.f;

        for (int kc = 0; kc < 16; kc++) {
            __syncthreads();
#pragma unroll
            for (int p = 0; p < 4; p++) {
                int o = p * 64 + (t >> 2);
                int kq = (t & 3) * 4;
                float4 v = *reinterpret_cast<const float4*>(&W_z[o * 256 + kc * 16 + kq]);
                Bs[(kq + 0) * SB + o] = v.x;
                Bs[(kq + 1) * SB + o] = v.y;
                Bs[(kq + 2) * SB + o] = v.z;
                Bs[(kq + 3) * SB + o] = v.w;
            }
            __syncthreads();
            const float* Ab;
            int astr, koff;
            if (kc < 4) { Ab = hH;  astr = 64;  koff = kc * 16; }
            else        { Ab = hhu; astr = 192; koff = kc * 16 - 64; }
#pragma unroll
            for (int k = 0; k < 16; k++) {
                float a[4], b[16];
#pragma unroll
                for (int j = 0; j < 4; j++) a[j] = Ab[(ty * 4 + j) * astr + koff + k];
#pragma unroll
                for (int g = 0; g < 4; g++)
#pragma unroll
                    for (int m = 0; m < 4; m++) b[g * 4 + m] = Bs[k * SB + g * 64 + tx * 4 + m];
#pragma unroll
                for (int j = 0; j < 4; j++)
#pragma unroll
                    for (int m = 0; m < 16; m++) acc[j][m] = fmaf(a[j], b[m], acc[j][m]);
            }
        }
        // epilogue: softmax over groups {h_H, h_L, h_R, u}, gated combine, store
#pragma unroll
        for (int j = 0; j < 4; j++) {
            int i = ty * 4 + j;
            float res[4];
#pragma unroll
            for (int m = 0; m < 4; m++) {
                int h = tx * 4 + m;
                float v0 = acc[j][0 * 4 + m] + __ldg(b_z +   0 + h);
                float v1 = acc[j][1 * 4 + m] + __ldg(b_z +  64 + h);
                float v2 = acc[j][2 * 4 + m] + __ldg(b_z + 128 + h);
                float v3 = acc[j][3 * 4 + m] + __ldg(b_z + 192 + h);
                float mx = fmaxf(fmaxf(v0, v1), fmaxf(v2, v3));
                float e0 = __expf(v0 - mx), e1 = __expf(v1 - mx);
                float e2 = __expf(v2 - mx), e3 = __expf(v3 - mx);
                float inv = 1.f / (e0 + e1 + e2 + e3);
                float hhv = hH[i * 64 + h];
                float hlv = hhu[i * 192 + h];
                float hrv = hhu[i * 192 + 64 + h];
                float uv  = hhu[i * 192 + 128 + h];
                res[m] = (e0 * hhv + e1 * hlv + e2 * hrv + e3 * uv) * inv;
            }
            *reinterpret_cast<float4*>(&up_out[(size_t)(r0 + i) * 64 + tx * 4]) =
                make_float4(res[0], res[1], res[2], res[3]);
        }
    }
}

static const int SMEM_BYTES =
    (64 * 192 + 64 * 192 + 64 * 64 + 16 * SB + 64 * 8 + 64 * 8 + 64) * (int)sizeof(float);

extern "C" void kernel_launch(void* const* d_in, const int* in_sizes, int n_in,
                              void* d_out, int out_size) {
    const float* contents = (const float*)d_in[0];
    const float* W_u = (const float*)d_in[1];
    const float* b_u = (const float*)d_in[2];
    const float* W_r = (const float*)d_in[3];
    const float* b_r = (const float*)d_in[4];
    const float* W_h = (const float*)d_in[5];
    const float* b_h = (const float*)d_in[6];
    const float* W_z = (const float*)d_in[7];
    const float* b_z = (const float*)d_in[8];
    float* out = (float*)d_out;

    float* upA = nullptr;
    float* upB = nullptr;
    cudaGetSymbolAddress((void**)&upA, g_upA);
    cudaGetSymbolAddress((void**)&upB, g_upB);

    cudaFuncSetAttribute(grnn_level_kernel,
                         cudaFuncAttributeMaxDynamicSharedMemorySize, SMEM_BYTES);

    // Level 12 (top): up = u
    {
        int n = 64 << 12;                      // 262144
        size_t off = (size_t)64 * ((1 << 12) - 1) * 7;
        int total = n * 64;
        grnn_top_kernel<<<(total + NTHR - 1) / NTHR, NTHR>>>(contents + off, W_u, b_u, upA, n);
    }

    // Levels 11..0 (ping-pong: odd j -> upB, even j -> upA; j==0 -> d_out)
    const float* prev = upA;
    for (int j = 11; j >= 0; j--) {
        int n = 64 << j;
        size_t off = (size_t)64 * ((1 << j) - 1) * 7;
        float* outp = (j == 0) ? out : ((j & 1) ? upB : upA);
        grnn_level_kernel<<<n / 64, NTHR, SMEM_BYTES>>>(
            contents + off, prev, outp,
            W_u, b_u, W_r, b_r, W_h, b_h, W_z, b_z);
        prev = outp;
    }
}

// round 2
// speedup vs baseline: 1.0001x; 1.0001x over previous
#include <cuda_runtime.h>
#include <cuda_bf16.h>
#include <math.h>

// GRNNTransformGated: 13-level binary-tree GRNN.
// B=64, LVLS=13, F=7, H=64. SIZES[j] = 64<<j, OFFS[j] = 64*((1<<j)-1).
//
// Level j (j = 12..0):
//   u   = relu(c @ W_u^T + b_u)                        (n,64)
//   j==12: up = u
//   hhu = [up[0::2], up[1::2], u]                      (n,192)
//   r   = sigmoid(hhu @ W_r^T + b_r)                   (n,192)
//   h_H = relu((r*hhu) @ W_h^T + b_h)                  (n,64)
//   z   = [h_H, hhu] @ W_z^T + b_z                     (n,256)
//   g   = softmax(z.reshape(n,4,64), axis=1)
//   up  = g0*h_H + g1*h_L + g2*h_R + g3*u              (n,64)

#define NTHR 256
#define SB 260   // Bs row stride (floats), padded vs 256 for bank spread

// Scratch ping-pong buffers (device globals: allocation-free).
__device__ float g_upA[262144 * 64];   // 67 MB
__device__ float g_upB[131072 * 64];   // 33.5 MB

// ---------------- top level (j=12): up = relu(c @ W_u^T + b_u) ----------------
__global__ void grnn_top_kernel(const float* __restrict__ contents,
                                const float* __restrict__ W_u,
                                const float* __restrict__ b_u,
                                float* __restrict__ up, int n) {
    int idx = blockIdx.x * blockDim.x + threadIdx.x;
    if (idx >= n * 64) return;
    int i = idx >> 6, h = idx & 63;
    const float* c = contents + (size_t)i * 7;
    const float* w = W_u + h * 7;
    float acc = b_u[h];
#pragma unroll
    for (int f = 0; f < 7; f++) acc = fmaf(__ldg(c + f), __ldg(w + f), acc);
    up[idx] = fmaxf(acc, 0.f);
}

// ---------------- fused level kernel: 64 rows per block ----------------
__global__ __launch_bounds__(NTHR) void grnn_level_kernel(
    const float* __restrict__ contents,  // n x 7 (already offset to this level)
    const float* __restrict__ up_prev,   // 2n x 64
    float* __restrict__ up_out,          // n x 64
    const float* __restrict__ W_u, const float* __restrict__ b_u,
    const float* __restrict__ W_r, const float* __restrict__ b_r,
    const float* __restrict__ W_h, const float* __restrict__ b_h,
    const float* __restrict__ W_z, const float* __restrict__ b_z)
{
    extern __shared__ float sm[];
    float* hhu = sm;                     // 64*192 = 12288
    float* rx  = hhu + 64 * 192;         // 64*192 = 12288
    float* hH  = rx  + 64 * 192;         // 64*64  = 4096
    float* Bs  = hH  + 64 * 64;          // 16*SB  = 4160
    float* cs  = Bs  + 16 * SB;          // 64*8   = 512
    float* wu  = cs  + 64 * 8;           // 64*8   = 512
    float* bus = wu  + 64 * 8;           // 64

    const int t  = threadIdx.x;
    const int tx = t & 15, ty = t >> 4;
    const int r0 = blockIdx.x * 64;

    // ---- phase 0: build hhu = [h_L | h_R | u] ----
    for (int idx = t; idx < 64 * 7; idx += NTHR) {
        int i = idx / 7, f = idx % 7;
        cs[i * 8 + f] = contents[(size_t)(r0 + i) * 7 + f];
        wu[i * 8 + f] = W_u[idx];
    }
    if (t < 64) bus[t] = b_u[t];
    for (int idx = t; idx < 64 * 128; idx += NTHR) {
        int i = idx >> 7, c = idx & 127;
        hhu[i * 192 + c] = up_prev[((size_t)2 * (r0 + i) + (c >> 6)) * 64 + (c & 63)];
    }
    __syncthreads();
#pragma unroll
    for (int p = 0; p < 16; p++) {
        int idx = t + p * NTHR;
        int i = idx >> 6, h = idx & 63;
        float acc = bus[h];
#pragma unroll
        for (int f = 0; f < 7; f++) acc = fmaf(cs[i * 8 + f], wu[h * 8 + f], acc);
        hhu[i * 192 + 128 + h] = fmaxf(acc, 0.f);
    }
    __syncthreads();

    // ---- phase 1: rx = sigmoid(hhu @ W_r^T + b_r) * hhu   (O=192, K=192) ----
    {
        float acc[4][12];
#pragma unroll
        for (int j = 0; j < 4; j++)
#pragma unroll
            for (int m = 0; m < 12; m++) acc[j][m] = 0.f;

        for (int kc = 0; kc < 12; kc++) {
            __syncthreads();
#pragma unroll
            for (int p = 0; p < 3; p++) {
                int o = p * 64 + (t >> 2);
                int kq = (t & 3) * 4;
                float4 v = *reinterpret_cast<const float4*>(&W_r[o * 192 + kc * 16 + kq]);
                Bs[(kq + 0) * SB + o] = v.x;
                Bs[(kq + 1) * SB + o] = v.y;
                Bs[(kq + 2) * SB + o] = v.z;
                Bs[(kq + 3) * SB + o] = v.w;
            }
            __syncthreads();
#pragma unroll
            for (int k = 0; k < 16; k++) {
                float a[4], b[12];
#pragma unroll
                for (int j = 0; j < 4; j++) a[j] = hhu[(ty * 4 + j) * 192 + kc * 16 + k];
#pragma unroll
                for (int m = 0; m < 12; m++) b[m] = Bs[k * SB + tx * 12 + m];
#pragma unroll
                for (int j = 0; j < 4; j++)
#pragma unroll
                    for (int m = 0; m < 12; m++) acc[j][m] = fmaf(a[j], b[m], acc[j][m]);
            }
        }
        __syncthreads();
#pragma unroll
        for (int j = 0; j < 4; j++)
#pragma unroll
            for (int m = 0; m < 12; m++) {
                int i = ty * 4 + j, o = tx * 12 + m;
                float rv = 1.f / (1.f + __expf(-(acc[j][m] + __ldg(b_r + o))));
                rx[i * 192 + o] = rv * hhu[i * 192 + o];
            }
    }
    __syncthreads();

    // ---- phase 2: h_H = relu(rx @ W_h^T + b_h)   (O=64, K=192) ----
    {
        float acc[4][4];
#pragma unroll
        for (int j = 0; j < 4; j++)
#pragma unroll
            for (int m = 0; m < 4; m++) acc[j][m] = 0.f;

        for (int kc = 0; kc < 12; kc++) {
            __syncthreads();
            {
                int o = t >> 2;
                int kq = (t & 3) * 4;
                float4 v = *reinterpret_cast<const float4*>(&W_h[o * 192 + kc * 16 + kq]);
                Bs[(kq + 0) * SB + o] = v.x;
                Bs[(kq + 1) * SB + o] = v.y;
                Bs[(kq + 2) * SB + o] = v.z;
                Bs[(kq + 3) * SB + o] = v.w;
            }
            __syncthreads();
#pragma unroll
            for (int k = 0; k < 16; k++) {
                float a[4], b[4];
#pragma unroll
                for (int j = 0; j < 4; j++) a[j] = rx[(ty * 4 + j) * 192 + kc * 16 + k];
#pragma unroll
                for (int m = 0; m < 4; m++) b[m] = Bs[k * SB + tx * 4 + m];
#pragma unroll
                for (int j = 0; j < 4; j++)
#pragma unroll
                    for (int m = 0; m < 4; m++) acc[j][m] = fmaf(a[j], b[m], acc[j][m]);
            }
        }
        __syncthreads();
#pragma unroll
        for (int j = 0; j < 4; j++)
#pragma unroll
            for (int m = 0; m < 4; m++) {
                int i = ty * 4 + j, o = tx * 4 + m;
                hH[i * 64 + o] = fmaxf(acc[j][m] + __ldg(b_h + o), 0.f);
            }
    }
    __syncthreads();

    // ---- phase 3: z = [h_H | hhu] @ W_z^T + b_z; softmax over 4 groups; combine ----
    {
        float acc[4][16];
#pragma unroll
        for (int j = 0; j < 4; j++)
#pragma unroll
            for (int m = 0; m < 16; m++) acc[j][m] = 0.f;

        for (int kc = 0; kc < 16; kc++) {
            __syncthreads();
#pragma unroll
            for (int p = 0; p < 4; p++) {
                int o = p * 64 + (t >> 2);
                int kq = (t & 3) * 4;
                float4 v = *reinterpret_cast<const float4*>(&W_z[o * 256 + kc * 16 + kq]);
                Bs[(kq + 0) * SB + o] = v.x;
                Bs[(kq + 1) * SB + o] = v.y;
                Bs[(kq + 2) * SB + o] = v.z;
                Bs[(kq + 3) * SB + o] = v.w;
            }
            __syncthreads();
            const float* Ab;
            int astr, koff;
            if (kc < 4) { Ab = hH;  astr = 64;  koff = kc * 16; }
            else        { Ab = hhu; astr = 192; koff = kc * 16 - 64; }
#pragma unroll
            for (int k = 0; k < 16; k++) {
                float a[4], b[16];
#pragma unroll
                for (int j = 0; j < 4; j++) a[j] = Ab[(ty * 4 + j) * astr + koff + k];
#pragma unroll
                for (int g = 0; g < 4; g++)
#pragma unroll
                    for (int m = 0; m < 4; m++) b[g * 4 + m] = Bs[k * SB + g * 64 + tx * 4 + m];
#pragma unroll
                for (int j = 0; j < 4; j++)
#pragma unroll
                    for (int m = 0; m < 16; m++) acc[j][m] = fmaf(a[j], b[m], acc[j][m]);
            }
        }
        // epilogue: softmax over groups {h_H, h_L, h_R, u}, gated combine, store
#pragma unroll
        for (int j = 0; j < 4; j++) {
            int i = ty * 4 + j;
            float res[4];
#pragma unroll
            for (int m = 0; m < 4; m++) {
                int h = tx * 4 + m;
                float v0 = acc[j][0 * 4 + m] + __ldg(b_z +   0 + h);
                float v1 = acc[j][1 * 4 + m] + __ldg(b_z +  64 + h);
                float v2 = acc[j][2 * 4 + m] + __ldg(b_z + 128 + h);
                float v3 = acc[j][3 * 4 + m] + __ldg(b_z + 192 + h);
                float mx = fmaxf(fmaxf(v0, v1), fmaxf(v2, v3));
                float e0 = __expf(v0 - mx), e1 = __expf(v1 - mx);
                float e2 = __expf(v2 - mx), e3 = __expf(v3 - mx);
                float inv = 1.f / (e0 + e1 + e2 + e3);
                float hhv = hH[i * 64 + h];
                float hlv = hhu[i * 192 + h];
                float hrv = hhu[i * 192 + 64 + h];
                float uv  = hhu[i * 192 + 128 + h];
                res[m] = (e0 * hhv + e1 * hlv + e2 * hrv + e3 * uv) * inv;
            }
            *reinterpret_cast<float4*>(&up_out[(size_t)(r0 + i) * 64 + tx * 4]) =
                make_float4(res[0], res[1], res[2], res[3]);
        }
    }
}

static const int SMEM_BYTES =
    (64 * 192 + 64 * 192 + 64 * 64 + 16 * SB + 64 * 8 + 64 * 8 + 64) * (int)sizeof(float);

extern "C" void kernel_launch(void* const* d_in, const int* in_sizes, int n_in,
                              void* d_out, int out_size) {
    const float* contents = (const float*)d_in[0];
    const float* W_u = (const float*)d_in[1];
    const float* b_u = (const float*)d_in[2];
    const float* W_r = (const float*)d_in[3];
    const float* b_r = (const float*)d_in[4];
    const float* W_h = (const float*)d_in[5];
    const float* b_h = (const float*)d_in[6];
    const float* W_z = (const float*)d_in[7];
    const float* b_z = (const float*)d_in[8];
    float* out = (float*)d_out;

    float* upA = nullptr;
    float* upB = nullptr;
    cudaGetSymbolAddress((void**)&upA, g_upA);
    cudaGetSymbolAddress((void**)&upB, g_upB);

    cudaFuncSetAttribute(grnn_level_kernel,
                         cudaFuncAttributeMaxDynamicSharedMemorySize, SMEM_BYTES);

    // Level 12 (top): up = u
    {
        int n = 64 << 12;                      // 262144
        size_t off = (size_t)64 * ((1 << 12) - 1) * 7;
        int total = n * 64;
        grnn_top_kernel<<<(total + NTHR - 1) / NTHR, NTHR>>>(contents + off, W_u, b_u, upA, n);
    }

    // Levels 11..0 (ping-pong: odd j -> upB, even j -> upA; j==0 -> d_out)
    const float* prev = upA;
    for (int j = 11; j >= 0; j--) {
        int n = 64 << j;
        size_t off = (size_t)64 * ((1 << j) - 1) * 7;
        float* outp = (j == 0) ? out : ((j & 1) ? upB : upA);
        grnn_level_kernel<<<n / 64, NTHR, SMEM_BYTES>>>(
            contents + off, prev, outp,
            W_u, b_u, W_r, b_r, W_h, b_h, W_z, b_z);
        prev = outp;
    }
}

// round 4
// speedup vs baseline: 1.0474x; 1.0473x over previous
#include <cuda_runtime.h>
#include <math.h>

// GRNNTransformGated: 13-level binary-tree GRNN, fp32 with packed f32x2 FMA.
// B=64, LVLS=13, F=7, H=64. SIZES[j] = 64<<j, OFFS[j] = 64*((1<<j)-1).

#define NTHR 256
#define SB 260   // Bs row stride (floats); even -> 8B alignment for paired loads

// Scratch ping-pong buffers (device globals: allocation-free).
__device__ float g_upA[262144 * 64];
__device__ float g_upB[131072 * 64];

// ---------- packed f32x2 helpers (Blackwell base ISA, PTX-only) ----------
__device__ __forceinline__ unsigned long long pk2(float a, float b) {
    unsigned long long r;
    asm("mov.b64 %0, {%1, %2};" : "=l"(r) : "f"(a), "f"(b));
    return r;
}
__device__ __forceinline__ float2 upk2(unsigned long long v) {
    float2 f;
    asm("mov.b64 {%0, %1}, %2;" : "=f"(f.x), "=f"(f.y) : "l"(v));
    return f;
}
__device__ __forceinline__ unsigned long long fma2(unsigned long long a,
                                                   unsigned long long b,
                                                   unsigned long long c) {
    unsigned long long d;
    asm("fma.rn.f32x2 %0, %1, %2, %3;" : "=l"(d) : "l"(a), "l"(b), "l"(c));
    return d;
}

// ---------------- top level (j=12): up = relu(c @ W_u^T + b_u) ----------------
__global__ void grnn_top_kernel(const float* __restrict__ contents,
                                const float* __restrict__ W_u,
                                const float* __restrict__ b_u,
                                float* __restrict__ up, int n) {
    int idx = blockIdx.x * blockDim.x + threadIdx.x;
    if (idx >= n * 64) return;
    int i = idx >> 6, h = idx & 63;
    const float* c = contents + (size_t)i * 7;
    const float* w = W_u + h * 7;
    float acc = b_u[h];
#pragma unroll
    for (int f = 0; f < 7; f++) acc = fmaf(__ldg(c + f), __ldg(w + f), acc);
    up[idx] = fmaxf(acc, 0.f);
}

// ---------------- fused level kernel: 64 rows per block ----------------
__global__ __launch_bounds__(NTHR) void grnn_level_kernel(
    const float* __restrict__ contents,
    const float* __restrict__ up_prev,
    float* __restrict__ up_out,
    const float* __restrict__ W_u, const float* __restrict__ b_u,
    const float* __restrict__ W_r, const float* __restrict__ b_r,
    const float* __restrict__ W_h, const float* __restrict__ b_h,
    const float* __restrict__ W_z, const float* __restrict__ b_z)
{
    extern __shared__ float sm[];
    float* hhu = sm;                     // 64*192
    float* rx  = hhu + 64 * 192;         // 64*192
    float* hH  = rx  + 64 * 192;         // 64*64
    float* Bs0 = hH  + 64 * 64;          // 16*SB
    float* Bs1 = Bs0 + 16 * SB;          // 16*SB
    float* cs  = Bs1 + 16 * SB;          // 64*8
    float* wu  = cs  + 64 * 8;           // 64*8
    float* bus = wu  + 64 * 8;           // 64

    const int t  = threadIdx.x;
    const int tx = t & 15, ty = t >> 4;
    const int r0 = blockIdx.x * 64;

    // ---- phase 0: build hhu = [h_L | h_R | u] ----
    for (int idx = t; idx < 64 * 7; idx += NTHR) {
        int i = idx / 7, f = idx % 7;
        cs[i * 8 + f] = contents[(size_t)(r0 + i) * 7 + f];
        wu[i * 8 + f] = W_u[idx];
    }
    if (t < 64) bus[t] = b_u[t];
    for (int idx = t; idx < 64 * 128; idx += NTHR) {
        int i = idx >> 7, c = idx & 127;
        hhu[i * 192 + c] = up_prev[((size_t)2 * (r0 + i) + (c >> 6)) * 64 + (c & 63)];
    }
    __syncthreads();
#pragma unroll
    for (int p = 0; p < 16; p++) {
        int idx = t + p * NTHR;
        int i = idx >> 6, h = idx & 63;
        float acc = bus[h];
#pragma unroll
        for (int f = 0; f < 7; f++) acc = fmaf(cs[i * 8 + f], wu[h * 8 + f], acc);
        hhu[i * 192 + 128 + h] = fmaxf(acc, 0.f);
    }
    __syncthreads();

    // ---- phase 1: rx = sigmoid(hhu @ W_r^T + b_r) * hhu   (O=192, K=192) ----
    {
        unsigned long long acc2[4][6];
#pragma unroll
        for (int j = 0; j < 4; j++)
#pragma unroll
            for (int m = 0; m < 6; m++) acc2[j][m] = 0ull;

        // stage kc into buffer B
        auto stage1 = [&](float* B, int kc) {
#pragma unroll
            for (int p = 0; p < 3; p++) {
                int o = p * 64 + (t >> 2), kq = (t & 3) * 4;
                float4 v = *reinterpret_cast<const float4*>(&W_r[o * 192 + kc * 16 + kq]);
                B[(kq + 0) * SB + o] = v.x; B[(kq + 1) * SB + o] = v.y;
                B[(kq + 2) * SB + o] = v.z; B[(kq + 3) * SB + o] = v.w;
            }
        };
        stage1(Bs0, 0);
        __syncthreads();
        for (int kc = 0; kc < 12; kc++) {
            float* Bc = (kc & 1) ? Bs1 : Bs0;
            float* Bn = (kc & 1) ? Bs0 : Bs1;
            if (kc + 1 < 12) stage1(Bn, kc + 1);
#pragma unroll
            for (int k = 0; k < 16; k++) {
                unsigned long long pa[4], b2[6];
#pragma unroll
                for (int j = 0; j < 4; j++) {
                    float a = hhu[(ty * 4 + j) * 192 + kc * 16 + k];
                    pa[j] = pk2(a, a);
                }
#pragma unroll
                for (int m = 0; m < 6; m++)
                    b2[m] = *reinterpret_cast<const unsigned long long*>(&Bc[k * SB + tx * 12 + 2 * m]);
#pragma unroll
                for (int j = 0; j < 4; j++)
#pragma unroll
                    for (int m = 0; m < 6; m++) acc2[j][m] = fma2(pa[j], b2[m], acc2[j][m]);
            }
            __syncthreads();
        }
#pragma unroll
        for (int j = 0; j < 4; j++)
#pragma unroll
            for (int m = 0; m < 6; m++) {
                int i = ty * 4 + j, o = tx * 12 + 2 * m;
                float2 v = upk2(acc2[j][m]);
                float r0v = 1.f / (1.f + __expf(-(v.x + __ldg(b_r + o))));
                float r1v = 1.f / (1.f + __expf(-(v.y + __ldg(b_r + o + 1))));
                rx[i * 192 + o]     = r0v * hhu[i * 192 + o];
                rx[i * 192 + o + 1] = r1v * hhu[i * 192 + o + 1];
            }
    }

    // ---- phase 2: h_H = relu(rx @ W_h^T + b_h)   (O=64, K=192) ----
    {
        unsigned long long acc2[4][2];
#pragma unroll
        for (int j = 0; j < 4; j++) { acc2[j][0] = 0ull; acc2[j][1] = 0ull; }

        auto stage2 = [&](float* B, int kc) {
            int o = t >> 2, kq = (t & 3) * 4;
            float4 v = *reinterpret_cast<const float4*>(&W_h[o * 192 + kc * 16 + kq]);
            B[(kq + 0) * SB + o] = v.x; B[(kq + 1) * SB + o] = v.y;
            B[(kq + 2) * SB + o] = v.z; B[(kq + 3) * SB + o] = v.w;
        };
        stage2(Bs0, 0);
        __syncthreads();
        for (int kc = 0; kc < 12; kc++) {
            float* Bc = (kc & 1) ? Bs1 : Bs0;
            float* Bn = (kc & 1) ? Bs0 : Bs1;
            if (kc + 1 < 12) stage2(Bn, kc + 1);
#pragma unroll
            for (int k = 0; k < 16; k++) {
                unsigned long long pa[4], b2[2];
#pragma unroll
                for (int j = 0; j < 4; j++) {
                    float a = rx[(ty * 4 + j) * 192 + kc * 16 + k];
                    pa[j] = pk2(a, a);
                }
#pragma unroll
                for (int m = 0; m < 2; m++)
                    b2[m] = *reinterpret_cast<const unsigned long long*>(&Bc[k * SB + tx * 4 + 2 * m]);
#pragma unroll
                for (int j = 0; j < 4; j++)
#pragma unroll
                    for (int m = 0; m < 2; m++) acc2[j][m] = fma2(pa[j], b2[m], acc2[j][m]);
            }
            __syncthreads();
        }
#pragma unroll
        for (int j = 0; j < 4; j++)
#pragma unroll
            for (int m = 0; m < 2; m++) {
                int i = ty * 4 + j, o = tx * 4 + 2 * m;
                float2 v = upk2(acc2[j][m]);
                hH[i * 64 + o]     = fmaxf(v.x + __ldg(b_h + o), 0.f);
                hH[i * 64 + o + 1] = fmaxf(v.y + __ldg(b_h + o + 1), 0.f);
            }
    }

    // ---- phase 3: z = [h_H | hhu] @ W_z^T + b_z; softmax; combine ----
    {
        unsigned long long acc2[4][8];
#pragma unroll
        for (int j = 0; j < 4; j++)
#pragma unroll
            for (int m = 0; m < 8; m++) acc2[j][m] = 0ull;

        auto stage3 = [&](float* B, int kc) {
#pragma unroll
            for (int p = 0; p < 4; p++) {
                int o = p * 64 + (t >> 2), kq = (t & 3) * 4;
                float4 v = *reinterpret_cast<const float4*>(&W_z[o * 256 + kc * 16 + kq]);
                B[(kq + 0) * SB + o] = v.x; B[(kq + 1) * SB + o] = v.y;
                B[(kq + 2) * SB + o] = v.z; B[(kq + 3) * SB + o] = v.w;
            }
        };
        stage3(Bs0, 0);
        __syncthreads();
        for (int kc = 0; kc < 16; kc++) {
            float* Bc = (kc & 1) ? Bs1 : Bs0;
            float* Bn = (kc & 1) ? Bs0 : Bs1;
            if (kc + 1 < 16) stage3(Bn, kc + 1);
            const float* Ab; int astr, koff;
            if (kc < 4) { Ab = hH;  astr = 64;  koff = kc * 16; }
            else        { Ab = hhu; astr = 192; koff = kc * 16 - 64; }
#pragma unroll
            for (int k = 0; k < 16; k++) {
                unsigned long long pa[4], b2[8];
#pragma unroll
                for (int j = 0; j < 4; j++) {
                    float a = Ab[(ty * 4 + j) * astr + koff + k];
                    pa[j] = pk2(a, a);
                }
#pragma unroll
                for (int g = 0; g < 4; g++)
#pragma unroll
                    for (int m = 0; m < 2; m++)
                        b2[g * 2 + m] = *reinterpret_cast<const unsigned long long*>(
                            &Bc[k * SB + g * 64 + tx * 4 + 2 * m]);
#pragma unroll
                for (int j = 0; j < 4; j++)
#pragma unroll
                    for (int m = 0; m < 8; m++) acc2[j][m] = fma2(pa[j], b2[m], acc2[j][m]);
            }
            __syncthreads();
        }
        // epilogue: softmax over groups {h_H, h_L, h_R, u}, gated combine, store
#pragma unroll
        for (int j = 0; j < 4; j++) {
            int i = ty * 4 + j;
            float zv[4][4];
#pragma unroll
            for (int g = 0; g < 4; g++)
#pragma unroll
                for (int p = 0; p < 2; p++) {
                    float2 v = upk2(acc2[j][g * 2 + p]);
                    zv[g][2 * p] = v.x; zv[g][2 * p + 1] = v.y;
                }
            float res[4];
#pragma unroll
            for (int m = 0; m < 4; m++) {
                int h = tx * 4 + m;
                float v0 = zv[0][m] + __ldg(b_z +   0 + h);
                float v1 = zv[1][m] + __ldg(b_z +  64 + h);
                float v2 = zv[2][m] + __ldg(b_z + 128 + h);
                float v3 = zv[3][m] + __ldg(b_z + 192 + h);
                float mx = fmaxf(fmaxf(v0, v1), fmaxf(v2, v3));
                float e0 = __expf(v0 - mx), e1 = __expf(v1 - mx);
                float e2 = __expf(v2 - mx), e3 = __expf(v3 - mx);
                float inv = 1.f / (e0 + e1 + e2 + e3);
                float hhv = hH[i * 64 + h];
                float hlv = hhu[i * 192 + h];
                float hrv = hhu[i * 192 + 64 + h];
                float uv  = hhu[i * 192 + 128 + h];
                res[m] = (e0 * hhv + e1 * hlv + e2 * hrv + e3 * uv) * inv;
            }
            *reinterpret_cast<float4*>(&up_out[(size_t)(r0 + i) * 64 + tx * 4]) =
                make_float4(res[0], res[1], res[2], res[3]);
        }
    }
}

static const int SMEM_BYTES =
    (64 * 192 + 64 * 192 + 64 * 64 + 2 * 16 * SB + 64 * 8 + 64 * 8 + 64) * (int)sizeof(float);

extern "C" void kernel_launch(void* const* d_in, const int* in_sizes, int n_in,
                              void* d_out, int out_size) {
    const float* contents = (const float*)d_in[0];
    const float* W_u = (const float*)d_in[1];
    const float* b_u = (const float*)d_in[2];
    const float* W_r = (const float*)d_in[3];
    const float* b_r = (const float*)d_in[4];
    const float* W_h = (const float*)d_in[5];
    const float* b_h = (const float*)d_in[6];
    const float* W_z = (const float*)d_in[7];
    const float* b_z = (const float*)d_in[8];
    float* out = (float*)d_out;

    float* upA = nullptr;
    float* upB = nullptr;
    cudaGetSymbolAddress((void**)&upA, g_upA);
    cudaGetSymbolAddress((void**)&upB, g_upB);

    cudaFuncSetAttribute(grnn_level_kernel,
                         cudaFuncAttributeMaxDynamicSharedMemorySize, SMEM_BYTES);

    // Level 12 (top): up = u
    {
        int n = 64 << 12;
        size_t off = (size_t)64 * ((1 << 12) - 1) * 7;
        int total = n * 64;
        grnn_top_kernel<<<(total + NTHR - 1) / NTHR, NTHR>>>(contents + off, W_u, b_u, upA, n);
    }

    // Levels 11..0
    const float* prev = upA;
    for (int j = 11; j >= 0; j--) {
        int n = 64 << j;
        size_t off = (size_t)64 * ((1 << j) - 1) * 7;
        float* outp = (j == 0) ? out : ((j & 1) ? upB : upA);
        grnn_level_kernel<<<n / 64, NTHR, SMEM_BYTES>>>(
            contents + off, prev, outp,
            W_u, b_u, W_r, b_r, W_h, b_h, W_z, b_z);
        prev = outp;
    }
}